// round 13
// baseline (speedup 1.0000x reference)
#include <cuda_runtime.h>
#include <cstdint>

typedef unsigned long long ULL;

// ---------------- constants ----------------
constexpr int B  = 4;
constexpr int C  = 64;
constexpr int H  = 128;
constexpr int W  = 128;
constexpr int Hp = 130;
constexpr int Wp = 130;
constexpr int O  = 64;
constexpr int N9 = 9;
constexpr int BHW = B * H * W;   // 65536

// fused prep-kernel block ranges (R6 plain prep)
constexpr int NB_OFF = BHW / 256;                 // 256 offset-conv blocks
constexpr int NB_PAD = B * 529;                   // 2116 pad-transpose blocks
constexpr int NB_PW  = (O * C * N9 + 255) / 256;  // 144 weight blocks
constexpr int PREP_SMEM = N9 * C * N9 * 8;        // 41472 B

// k_main smem layout (72 KB total, 2 blocks/SM): X double-buffered, W from gmem
constexpr int SM_X    = 0;        // 2 x 32768 : X[buf][64 c][128 px] 16B-chunk XOR swizzled
constexpr int SM_MIDX = 65536;    // 2 x 2048  : int4  [2][128]
constexpr int SM_MW   = 69632;    // 2 x 2048  : float4[2][128]
constexpr int SM_MAIN = 73728;

// ---------------- scratch (device globals; no allocs) ----------------
__device__ __align__(16) float g_xpad[B * Hp * Wp * C];   // NHWC zero-padded x0
__device__ __align__(16) ULL   g_wTn2[N9 * C * O];        // [n][c][o] -> (w, w) pair
__device__ __align__(16) int4   g_midx[N9 * BHW];         // [n][P] corner offsets
__device__ __align__(16) float4 g_mw[N9 * BHW];           // [n][P] bilinear weights

// ---------------- packed f32x2 helpers ----------------
__device__ __forceinline__ ULL ffma2(ULL a, ULL b, ULL c) {
    ULL d;
    asm("fma.rn.f32x2 %0, %1, %2, %3;" : "=l"(d) : "l"(a), "l"(b), "l"(c));
    return d;
}
__device__ __forceinline__ ULL pack2(float lo, float hi) {
    ULL d;
    asm("mov.b64 %0, {%1, %2};" : "=l"(d) : "f"(lo), "f"(hi));
    return d;
}
__device__ __forceinline__ void unpack2(ULL v, float& lo, float& hi) {
    asm("mov.b64 {%0, %1}, %2;" : "=f"(lo), "=f"(hi) : "l"(v));
}

// ============================================================================
// Fused prep kernel (offset conv + meta | pad/transpose | weight reshuffle)
// (R6 plain version — best measured)
// ============================================================================
__global__ void __launch_bounds__(256) k_prep(const float* __restrict__ x0,
                                              const float* __restrict__ x1,
                                              const float* __restrict__ p_w,
                                              const float* __restrict__ p_b,
                                              const float* __restrict__ conv_w) {
    extern __shared__ char dsm[];
    int t = threadIdx.x;
    int bid = blockIdx.x;

    if (bid < NB_OFF) {
        // ---------------- offset conv + metadata ----------------
        ULL* wsm = (ULL*)dsm;   // [n][c][kk] paired weights, 41472 B
        for (int e = t; e < N9 * C * N9; e += 256)
            wsm[e] = pack2(p_w[e], p_w[e + 5184]);
        __syncthreads();

        int P = bid * 256 + t;
        int b = P >> 14;
        int rem = P & 16383;
        int i = rem >> 7;
        int j = rem & 127;

        ULL acc[9];
        #pragma unroll
        for (int n = 0; n < 9; n++) acc[n] = pack2(p_b[n], p_b[n + 9]);

        const float* x1b = x1 + (b * C * H * W) + i * W + j;
        bool rok0 = (i > 0), rok2 = (i < H - 1), cok0 = (j > 0), cok2 = (j < W - 1);

        #pragma unroll 2
        for (int c = 0; c < C; c++) {
            const float* xc = x1b + c * (H * W);
            float v[9];
            #pragma unroll
            for (int di = 0; di < 3; di++) {
                bool rok = (di == 0) ? rok0 : ((di == 2) ? rok2 : true);
                const float* xr = xc + (di - 1) * W;
                v[di * 3 + 0] = (rok && cok0) ? xr[-1] : 0.f;
                v[di * 3 + 1] = rok ? xr[0] : 0.f;
                v[di * 3 + 2] = (rok && cok2) ? xr[1] : 0.f;
            }
            ULL vd[9];
            #pragma unroll
            for (int k = 0; k < 9; k++) vd[k] = pack2(v[k], v[k]);
            const ULL* wrow = &wsm[c * N9];
            #pragma unroll
            for (int n = 0; n < 9; n++) {
                const ULL* wn = wrow + n * (C * N9);
                #pragma unroll
                for (int k = 0; k < 9; k++)
                    acc[n] = ffma2(vd[k], wn[k], acc[n]);
            }
        }

        int xb130 = b * 130;
        #pragma unroll
        for (int n = 0; n < 9; n++) {
            float ox, oy;
            unpack2(acc[n], ox, oy);
            float px = (float)(i + n / 3) + ox;
            float py = (float)(j + n % 3) + oy;
            float fx = floorf(px), fy = floorf(py);
            int qltx = max(min((int)fx, Hp - 1), 0);
            int qlty = max(min((int)fy, Wp - 1), 0);
            int qrbx = max(min((int)fx + 1, Hp - 1), 0);
            int qrby = max(min((int)fy + 1, Wp - 1), 0);
            float pxc = fminf(fmaxf(px, 0.f), (float)(Hp - 1));
            float pyc = fminf(fmaxf(py, 0.f), (float)(Wp - 1));
            float ax = 1.f + (float)qltx - pxc;
            float bx = 1.f - (float)qrbx + pxc;
            float ay = 1.f + (float)qlty - pyc;
            float by = 1.f - (float)qrby + pyc;
            int4 idx;
            idx.x = ((xb130 + qltx) * 130 + qlty) * 64;
            idx.y = ((xb130 + qrbx) * 130 + qrby) * 64;
            idx.z = ((xb130 + qltx) * 130 + qrby) * 64;
            idx.w = ((xb130 + qrbx) * 130 + qlty) * 64;
            float4 wv;
            wv.x = ax * ay;
            wv.y = bx * by;
            wv.z = ax * by;
            wv.w = bx * ay;
            g_midx[n * BHW + P] = idx;
            g_mw[n * BHW + P]   = wv;
        }
    } else if (bid < NB_OFF + NB_PAD) {
        // ---------------- pad + transpose ----------------
        float (*tile)[33] = (float(*)[33])dsm;
        int bp = bid - NB_OFF;
        int b  = bp / 529;
        int p0 = (bp - b * 529) * 32;
        int tx = t & 31;
        int ty = t >> 5;

        #pragma unroll
        for (int cc = ty; cc < 64; cc += 8) {
            int p = p0 + tx;
            float v = 0.f;
            if (p < Hp * Wp) {
                int y = p / Wp, x = p - (p / Wp) * Wp;
                if (y >= 1 && y <= H && x >= 1 && x <= W)
                    v = x0[((b * C + cc) * H + (y - 1)) * W + (x - 1)];
            }
            tile[cc][tx] = v;
        }
        __syncthreads();

        int base = (b * Hp * Wp + p0) * 64;
        for (int e = t; e < 32 * 64; e += 256) {
            int pl = e >> 6, c = e & 63;
            if (p0 + pl < Hp * Wp)
                g_xpad[base + pl * 64 + c] = tile[c][pl];
        }
    } else {
        // ---------------- conv_w reshuffle ----------------
        int idx = (bid - NB_OFF - NB_PAD) * 256 + t;
        if (idx < O * C * N9) {
            int o = idx / (C * N9);
            int c = (idx / N9) % C;
            int n = idx % N9;
            float w = conv_w[idx];
            g_wTn2[(n * C + c) * O + o] = pack2(w, w);
        }
    }
}

// ============================================================================
// k_main: 1-row blocks (128 px x 64 o), 256 threads, 2 blocks/SM.
// X DOUBLE-BUFFERED in smem; W GEMM operand read directly from gmem via
// uniform __ldg (L1-cached, shared by co-resident blocks). Gather for tap n+1
// is interleaved INSIDE tap n's GEMM in 2-px quarters: issue corner LDGs,
// run 16 k-steps (hides L2 latency), blend+store. ONE barrier per tap.
// ============================================================================
__global__ void __launch_bounds__(256, 2) k_main(float* __restrict__ out) {
    extern __shared__ char dsm[];
    char*   xbufs  = dsm + SM_X;                // [2][64c][512B]
    int4*   midx_s = (int4*)(dsm + SM_MIDX);    // [2][128]
    float4* mw_s   = (float4*)(dsm + SM_MW);    // [2][128]

    int t = threadIdx.x;
    int warp = t >> 5;
    int lane = t & 31;
    int bid = blockIdx.x;             // 512 blocks
    int i = bid & 127;
    int b = bid >> 7;
    int pixbase = (b * H + i) * W;

    int lg = t & 15;                  // gather: channel quad (c = lg*4)
    int hg = t >> 4;                  // gather: 8-px group (px = hg*8..+7)
    int xorc = lg & 7;

    ULL acc[8][2];
    #pragma unroll
    for (int r = 0; r < 8; r++) { acc[r][0] = 0ull; acc[r][1] = 0ull; }

    const float* xbg = g_xpad + lg * 4;

    // ---- prologue: stage meta(0) -> buf0, meta(1) -> buf1 ----
    if (t < 128) {
        midx_s[t]       = g_midx[pixbase + t];
        midx_s[128 + t] = g_midx[BHW + pixbase + t];
    } else {
        mw_s[t - 128]       = g_mw[pixbase + (t - 128)];
        mw_s[128 + (t - 128)] = g_mw[BHW + pixbase + (t - 128)];
    }
    __syncthreads();

    // ---- prologue gather: tap 0 -> X buf 0 (R8 gather shape) ----
    #pragma unroll 1
    for (int j = 0; j < 2; j++) {
        float rr[4][4];
        #pragma unroll
        for (int jj = 0; jj < 4; jj++) {
            int px = hg * 8 + j * 4 + jj;
            int4   id = midx_s[px];
            float4 g  = mw_s[px];
            float4 v0 = *(const float4*)(xbg + id.x);
            float4 v1 = *(const float4*)(xbg + id.y);
            float4 v2 = *(const float4*)(xbg + id.z);
            float4 v3 = *(const float4*)(xbg + id.w);
            rr[jj][0] = g.x * v0.x + g.y * v1.x + g.z * v2.x + g.w * v3.x;
            rr[jj][1] = g.x * v0.y + g.y * v1.y + g.z * v2.y + g.w * v3.y;
            rr[jj][2] = g.x * v0.z + g.y * v1.z + g.z * v2.z + g.w * v3.z;
            rr[jj][3] = g.x * v0.w + g.y * v1.w + g.z * v2.w + g.w * v3.w;
        }
        int chunk = (hg * 2 + j) ^ xorc;
        #pragma unroll
        for (int q = 0; q < 4; q++)
            *(float4*)(xbufs + ((lg * 4 + q) << 9) + (chunk << 4)) =
                make_float4(rr[0][q], rr[1][q], rr[2][q], rr[3][q]);
    }
    __syncthreads();

    // ---- tap loop: GEMM(n) from buf cur interleaved with gather(n+1) -> nxt ----
    #pragma unroll 1
    for (int n = 0; n < 9; n++) {
        int cur = n & 1, nxt = cur ^ 1;
        const char* xcur = xbufs + cur * 32768;
        char*       xnxt = xbufs + nxt * 32768;
        const ULL*  wg   = g_wTn2 + n * 4096;       // gmem W slice for tap n
        bool do_g = (n < 8);

        // stage meta(n+2) into buf cur (meta(n) there is dead after tap n-1)
        if (n < 7) {
            if (t < 128) midx_s[cur * 128 + t] = g_midx[(n + 2) * BHW + pixbase + t];
            else         mw_s[cur * 128 + (t - 128)] = g_mw[(n + 2) * BHW + pixbase + (t - 128)];
        }

        float rr[4][4];
        #pragma unroll 1
        for (int q = 0; q < 4; q++) {
            // ---- issue corner LDGs for 2 px of tap n+1 (meta from buf nxt) ----
            float4 va0, va1, va2, va3, vb0, vb1, vb2, vb3, ga, gb;
            if (do_g) {
                int px0 = hg * 8 + q * 2;
                int4 ia = midx_s[nxt * 128 + px0];
                ga = mw_s[nxt * 128 + px0];
                int4 ib = midx_s[nxt * 128 + px0 + 1];
                gb = mw_s[nxt * 128 + px0 + 1];
                va0 = *(const float4*)(xbg + ia.x);
                va1 = *(const float4*)(xbg + ia.y);
                va2 = *(const float4*)(xbg + ia.z);
                va3 = *(const float4*)(xbg + ia.w);
                vb0 = *(const float4*)(xbg + ib.x);
                vb1 = *(const float4*)(xbg + ib.y);
                vb2 = *(const float4*)(xbg + ib.z);
                vb3 = *(const float4*)(xbg + ib.w);
            }

            // ---- GEMM: 16 k-steps (k = q*16 .. +15), W via uniform __ldg ----
            #pragma unroll
            for (int kk = 0; kk < 16; kk++) {
                int k = q * 16 + kk;
                int xk = (k >> 2) & 7;
                ulonglong2 xA = *(const ulonglong2*)(xcur + (k << 9) + ((lane ^ xk) << 4));
                const ulonglong2* wr = (const ulonglong2*)(wg + (k << 6) + (warp << 3));
                ulonglong2 w01 = __ldg(wr);
                ulonglong2 w23 = __ldg(wr + 1);
                ulonglong2 w45 = __ldg(wr + 2);
                ulonglong2 w67 = __ldg(wr + 3);
                acc[0][0] = ffma2(xA.x, w01.x, acc[0][0]);
                acc[0][1] = ffma2(xA.y, w01.x, acc[0][1]);
                acc[1][0] = ffma2(xA.x, w01.y, acc[1][0]);
                acc[1][1] = ffma2(xA.y, w01.y, acc[1][1]);
                acc[2][0] = ffma2(xA.x, w23.x, acc[2][0]);
                acc[2][1] = ffma2(xA.y, w23.x, acc[2][1]);
                acc[3][0] = ffma2(xA.x, w23.y, acc[3][0]);
                acc[3][1] = ffma2(xA.y, w23.y, acc[3][1]);
                acc[4][0] = ffma2(xA.x, w45.x, acc[4][0]);
                acc[4][1] = ffma2(xA.y, w45.x, acc[4][1]);
                acc[5][0] = ffma2(xA.x, w45.y, acc[5][0]);
                acc[5][1] = ffma2(xA.y, w45.y, acc[5][1]);
                acc[6][0] = ffma2(xA.x, w67.x, acc[6][0]);
                acc[6][1] = ffma2(xA.y, w67.x, acc[6][1]);
                acc[7][0] = ffma2(xA.x, w67.y, acc[7][0]);
                acc[7][1] = ffma2(xA.y, w67.y, acc[7][1]);
            }

            // ---- blend the 2 px; store 4-px chunk after odd quarters ----
            if (do_g) {
                int e = (q & 1) * 2;
                rr[e][0]     = ga.x * va0.x + ga.y * va1.x + ga.z * va2.x + ga.w * va3.x;
                rr[e][1]     = ga.x * va0.y + ga.y * va1.y + ga.z * va2.y + ga.w * va3.y;
                rr[e][2]     = ga.x * va0.z + ga.y * va1.z + ga.z * va2.z + ga.w * va3.z;
                rr[e][3]     = ga.x * va0.w + ga.y * va1.w + ga.z * va2.w + ga.w * va3.w;
                rr[e + 1][0] = gb.x * vb0.x + gb.y * vb1.x + gb.z * vb2.x + gb.w * vb3.x;
                rr[e + 1][1] = gb.x * vb0.y + gb.y * vb1.y + gb.z * vb2.y + gb.w * vb3.y;
                rr[e + 1][2] = gb.x * vb0.z + gb.y * vb1.z + gb.z * vb2.z + gb.w * vb3.z;
                rr[e + 1][3] = gb.x * vb0.w + gb.y * vb1.w + gb.z * vb2.w + gb.w * vb3.w;
                if (q & 1) {
                    int j = q >> 1;
                    int chunk = (hg * 2 + j) ^ xorc;
                    #pragma unroll
                    for (int q4 = 0; q4 < 4; q4++)
                        *(float4*)(xnxt + ((lg * 4 + q4) << 9) + (chunk << 4)) =
                            make_float4(rr[0][q4], rr[1][q4], rr[2][q4], rr[3][q4]);
                }
            }
        }
        __syncthreads();   // single barrier per tap
    }

    // ---- write out: o = warp*8+r; px lane*4..+3 (coalesced) ----
    float* ob = out + ((b * O + warp * 8) * H + i) * W + lane * 4;
    #pragma unroll
    for (int r = 0; r < 8; r++) {
        float4 v;
        unpack2(acc[r][0], v.x, v.y);
        unpack2(acc[r][1], v.z, v.w);
        *(float4*)(ob + r * (H * W)) = v;
    }
}

// ============================================================================
extern "C" void kernel_launch(void* const* d_in, const int* in_sizes, int n_in,
                              void* d_out, int out_size) {
    const float* x0     = (const float*)d_in[0];
    const float* x1     = (const float*)d_in[1];
    const float* p_w    = (const float*)d_in[2];
    const float* p_b    = (const float*)d_in[3];
    const float* conv_w = (const float*)d_in[4];
    float* out = (float*)d_out;

    cudaFuncSetAttribute(k_main, cudaFuncAttributeMaxDynamicSharedMemorySize, SM_MAIN);

    k_prep<<<NB_OFF + NB_PAD + NB_PW, 256, PREP_SMEM>>>(x0, x1, p_w, p_b, conv_w);
    k_main<<<B * H, 256, SM_MAIN>>>(out);
}